// round 10
// baseline (speedup 1.0000x reference)
#include <cuda_runtime.h>
#include <stdint.h>

#define NN 100000
#define NE 1000000
#define HDIM 128
#define NHEADS 4
#define NTBLK 32      // table-builder blocks prefixed onto prep grid
#define EPT 8         // edges per thread (prep + pass1)

// ---------------- device scratch ----------------
__device__ float2        g_acc2[NN];        // per-dst {A,B}: acc = A - scalars[d]*B
__device__ double        g_loss;
__device__ int2          g_nrec[NN];        // {float_as_int(scalars[i]), node_code}
__device__ unsigned char g_ecodes[NE];
__device__ float         g_T[NHEADS][32];   // raw head dots: [h][0..15]=TE, [h][16..31]=TN
__device__ float4        g_P4[256];         // {p_inc, p_keep, p2+p3, p3} per (ce<<4)|cn
__device__ unsigned      g_cnt1 = 0;        // table completion counter
__device__ unsigned      g_done = 0;        // pass2 completion counter

__device__ __forceinline__ void red_add_f2(float2* addr, float a, float b) {
    asm volatile("red.global.add.v2.f32 [%0], {%1, %2};"
                 :: "l"(addr), "f"(a), "f"(b) : "memory");
}

// ---------------- kernel A: tables (blocks 0..31, shared-staged) + prep (rest) ----------------
__global__ void __launch_bounds__(256) prep_tables_kernel(
        const int*   __restrict__ node_states,
        const int*   __restrict__ edge_states,
        const float* __restrict__ scalars,
        const float* __restrict__ combine_W,   // (256,128)
        const float* __restrict__ combine_b,   // (128,)
        const float* __restrict__ node_emb,    // (16,128)
        const float* __restrict__ edge_emb,    // (16,128)
        const float* __restrict__ keep_W,  const float* __restrict__ keep_b,
        const float* __restrict__ push_W,  const float* __restrict__ push_b,
        const float* __restrict__ pushn_W, const float* __restrict__ pushn_b,
        const float* __restrict__ inc_W,   const float* __restrict__ inc_b,
        const int*   __restrict__ training_step) {
    int tid = threadIdx.x;
    int blk = blockIdx.x;

    if (blk >= NTBLK) {
        // ---------------- prep: EPT edges + EPT nodes per thread, coalesced strides ----------------
        int base = (blk - NTBLK) * 256 * EPT + tid;   // lane-coalesced, stride 256
        int4 es[EPT];
        #pragma unroll
        for (int k = 0; k < EPT; k++) {
            int e = base + k * 256;
            if (e < NE) es[k] = __ldcs(reinterpret_cast<const int4*>(edge_states) + e);
        }
        #pragma unroll
        for (int k = 0; k < EPT; k++) {
            int e = base + k * 256;
            if (e < NE)
                g_ecodes[e] = (unsigned char)(es[k].x + 2 * es[k].y + 4 * es[k].z + 8 * es[k].w);
        }
        #pragma unroll
        for (int k = 0; k < EPT; k++) {
            int i = base + k * 256;
            if (i < NN) {
                int4 s = reinterpret_cast<const int4*>(node_states)[i];
                g_nrec[i] = make_int2(__float_as_int(scalars[i]),
                                      s.x + 2 * s.y + 4 * s.z + 8 * s.w);
                g_acc2[i] = make_float2(0.f, 0.f);
            }
        }
        if (base == 0) g_loss = 0.0;
        return;
    }

    // ---------------- table block b: M[b][:] = emb_row_b @ W_half, then 4 head dots ----------------
    __shared__ float sW[64 * HDIM];      // 32KB staging (2 stages of 64 rows)
    __shared__ float sEmb[HDIM];
    __shared__ float sD[NHEADS][HDIM];   // per-head direction vectors
    __shared__ float sPart[256];
    __shared__ float sRed[NHEADS][4];    // per-warp partials for head dots
    __shared__ int   sh_last;

    int b = blk, k = b & 15;
    int base = (b < 16) ? 0 : HDIM;
    const float* embrow = ((b < 16) ? edge_emb : node_emb) + k * HDIM;

    if (tid < HDIM) sEmb[tid] = embrow[tid];
    {   // load 4 head direction vectors (512 elems, 2 per thread)
        const float* Wh[NHEADS] = {inc_W, keep_W, push_W, pushn_W};
        #pragma unroll
        for (int t = tid; t < NHEADS * HDIM; t += 256) {
            int h = t >> 7, i = t & 127;
            sD[h][i] = Wh[h][2 * i] - Wh[h][2 * i + 1];
        }
    }
    __syncthreads();

    int j = tid & 127, half = tid >> 7;
    float acc = 0.f;
    #pragma unroll
    for (int stage = 0; stage < 2; stage++) {
        const float4* Wv = reinterpret_cast<const float4*>(combine_W + (base + stage * 64) * HDIM);
        float4* sWv = reinterpret_cast<float4*>(sW);
        #pragma unroll
        for (int t = 0; t < 8; t++)
            sWv[t * 256 + tid] = Wv[t * 256 + tid];
        __syncthreads();
        const float* eb = sEmb + stage * 64 + half * 32;
        const float* ws = sW + (half * 32) * HDIM + j;
        #pragma unroll
        for (int i = 0; i < 32; i++)
            acc = fmaf(eb[i], ws[i * HDIM], acc);
        __syncthreads();
    }
    sPart[tid] = acc;
    __syncthreads();

    if (tid < 128) {
        float m = sPart[tid] + sPart[tid + 128];
        float v0 = m * sD[0][tid], v1 = m * sD[1][tid];
        float v2 = m * sD[2][tid], v3 = m * sD[3][tid];
        #pragma unroll
        for (int o = 16; o > 0; o >>= 1) {
            v0 += __shfl_down_sync(0xFFFFFFFFu, v0, o);
            v1 += __shfl_down_sync(0xFFFFFFFFu, v1, o);
            v2 += __shfl_down_sync(0xFFFFFFFFu, v2, o);
            v3 += __shfl_down_sync(0xFFFFFFFFu, v3, o);
        }
        int w = tid >> 5;
        if ((tid & 31) == 0) {
            sRed[0][w] = v0; sRed[1][w] = v1; sRed[2][w] = v2; sRed[3][w] = v3;
        }
    }
    __syncthreads();
    if (tid < NHEADS)
        g_T[tid][b] = sRed[tid][0] + sRed[tid][1] + sRed[tid][2] + sRed[tid][3];

    __threadfence();
    __syncthreads();
    if (tid == 0) sh_last = (atomicAdd(&g_cnt1, 1u) == NTBLK - 1u);
    __syncthreads();
    if (!sh_last) return;

    // -------- finisher: constants + bake g_P4 --------
    __shared__ float sC[NHEADS];
    __shared__ float sT[NHEADS][32];
    const float* bh[NHEADS] = {inc_b, keep_b, push_b, pushn_b};
    if (tid < 128) {
        int h = tid >> 5, l = tid & 31;
        float c = combine_b[l] * sD[h][l]
                + combine_b[l + 32] * sD[h][l + 32]
                + combine_b[l + 64] * sD[h][l + 64]
                + combine_b[l + 96] * sD[h][l + 96];
        #pragma unroll
        for (int o = 16; o > 0; o >>= 1) c += __shfl_down_sync(0xFFFFFFFFu, c, o);
        if (l == 0) sC[h] = c + bh[h][0] - bh[h][1];
    }
    if (tid < NHEADS * 32) sT[tid >> 5][tid & 31] = g_T[tid >> 5][tid & 31];
    __syncthreads();

    int step = training_step[0];
    float tau = (step == -1) ? 0.1f
              : (1.0f + (0.1f - 1.0f) * fminf((float)step / 10000.0f, 1.0f));
    float invtau = 1.0f / tau;

    {
        int ce = tid >> 4, cn = tid & 15;
        float p[NHEADS];
        #pragma unroll
        for (int h = 0; h < NHEADS; h++) {
            float logit = (sT[h][ce] + sT[h][16 + cn] + sC[h]) * invtau;
            p[h] = 1.0f / (1.0f + __expf(-logit));
        }
        g_P4[tid] = make_float4(p[0], p[1], p[2] + p[3], p[3]);
    }
    if (tid == 0) g_cnt1 = 0;   // reset for next graph replay
}

// ---------------- kernel B: main edge pass, EPT edges/thread ----------------
__global__ void __launch_bounds__(256) pass1_kernel(const int* __restrict__ edge_index,
                                                    const int* __restrict__ brev,
                                                    const float* __restrict__ scalars,
                                                    const float* __restrict__ target,
                                                    float* __restrict__ out) {
    __shared__ float4 sP4[256];
    __shared__ float warp_sums[8];
    int tid = threadIdx.x;
    sP4[tid] = g_P4[tid];
    __syncthreads();

    int base = blockIdx.x * 256 * EPT + tid;
    float sq = 0.0f;

    int  rev[EPT], src[EPT], dst[EPT];
    float s[EPT];
    bool  v[EPT];
    #pragma unroll
    for (int k = 0; k < EPT; k++) {
        int e = base + k * 256;
        v[k] = (e < NE);
        if (v[k]) {
            rev[k] = brev[e];
            s[k] = scalars[e];
            if (e < NN) { src[k] = e; dst[k] = e; }
            else { src[k] = edge_index[e]; dst[k] = edge_index[NE + e]; }
        }
    }
    unsigned ce[EPT];
    #pragma unroll
    for (int k = 0; k < EPT; k++) if (v[k]) ce[k] = g_ecodes[rev[k]];
    int2 nr[EPT];
    #pragma unroll
    for (int k = 0; k < EPT; k++) if (v[k]) nr[k] = g_nrec[src[k]];

    #pragma unroll
    for (int k = 0; k < EPT; k++) {
        if (!v[k]) continue;
        int e = base + k * 256;
        float ssrc = __int_as_float(nr[k].x);
        float4 p = sP4[(ce[k] << 4) | (unsigned)nr[k].y];
        red_add_f2(&g_acc2[dst[k]], fmaf(p.z, s[k], p.w * ssrc), p.z);
        float ns = fmaf(s[k], p.y, p.x);
        out[e] = ns;
        if (e >= NN) { float d = target[e] - ns; sq = fmaf(d, d, sq); }
    }

    #pragma unroll
    for (int o = 16; o > 0; o >>= 1) sq += __shfl_down_sync(0xFFFFFFFFu, sq, o);
    int lane = tid & 31, wid = tid >> 5;
    if (lane == 0) warp_sums[wid] = sq;
    __syncthreads();
    if (wid == 0) {
        float vv = (lane < 8) ? warp_sums[lane] : 0.0f;
        #pragma unroll
        for (int o = 4; o > 0; o >>= 1) vv += __shfl_down_sync(0xFFFFFFFFu, vv, o);
        if (lane == 0 && vv != 0.0f) atomicAdd(&g_loss, (double)vv);
    }
}

// ---------------- kernel C: finalize first N + loss (4 elems/thread) ----------------
__global__ void __launch_bounds__(256) pass2_kernel(const float* __restrict__ scalars,
                                                    const float* __restrict__ target,
                                                    float* __restrict__ out,
                                                    int write_loss) {
    __shared__ float warp_sums[8];
    __shared__ int sh_last;
    int tid = threadIdx.x;
    int q = (blockIdx.x * blockDim.x + tid) * 4;

    float sq = 0.0f;
    if (q < NN) {                                  // NN % 4 == 0
        int p = q >> 1;
        float4 a01 = reinterpret_cast<const float4*>(g_acc2)[p];
        float4 a23 = reinterpret_cast<const float4*>(g_acc2)[p + 1];
        float4 o  = *reinterpret_cast<const float4*>(out + q);
        float4 sc = *reinterpret_cast<const float4*>(scalars + q);
        float4 tg = *reinterpret_cast<const float4*>(target + q);
        float ns0 = o.x + fmaf(-sc.x, a01.y, a01.x);
        float ns1 = o.y + fmaf(-sc.y, a01.w, a01.z);
        float ns2 = o.z + fmaf(-sc.z, a23.y, a23.x);
        float ns3 = o.w + fmaf(-sc.w, a23.w, a23.z);
        *reinterpret_cast<float4*>(out + q) = make_float4(ns0, ns1, ns2, ns3);
        float d0 = tg.x - ns0, d1 = tg.y - ns1, d2 = tg.z - ns2, d3 = tg.w - ns3;
        sq = fmaf(d0, d0, fmaf(d1, d1, fmaf(d2, d2, d3 * d3)));
    }

    #pragma unroll
    for (int o = 16; o > 0; o >>= 1) sq += __shfl_down_sync(0xFFFFFFFFu, sq, o);
    int lane = tid & 31, wid = tid >> 5;
    if (lane == 0) warp_sums[wid] = sq;
    __syncthreads();
    if (wid == 0) {
        float v = (lane < 8) ? warp_sums[lane] : 0.0f;
        #pragma unroll
        for (int o = 4; o > 0; o >>= 1) v += __shfl_down_sync(0xFFFFFFFFu, v, o);
        if (lane == 0) atomicAdd(&g_loss, (double)v);
    }

    if (tid == 0) {
        __threadfence();
        sh_last = (atomicAdd(&g_done, 1u) == gridDim.x - 1);
    }
    __syncthreads();
    if (sh_last && tid == 0) {
        if (write_loss) out[NE] = (float)(g_loss / (double)NE);
        g_done = 0;
    }
}

// ---------------- launcher ----------------
extern "C" void kernel_launch(void* const* d_in, const int* in_sizes, int n_in,
                              void* d_out, int out_size) {
    const int*   node_states = (const int*)  d_in[0];
    const int*   edge_states = (const int*)  d_in[1];
    const float* scalars     = (const float*)d_in[2];
    const int*   edge_index  = (const int*)  d_in[3];
    const int*   brev        = (const int*)  d_in[4];
    const float* batch_sc    = (const float*)d_in[5];
    const int*   train_step  = (const int*)  d_in[7];
    const float* node_emb    = (const float*)d_in[8];
    const float* edge_emb    = (const float*)d_in[9];
    const float* combine_W   = (const float*)d_in[10];
    const float* combine_b   = (const float*)d_in[11];
    const float* keep_W      = (const float*)d_in[12];
    const float* keep_b      = (const float*)d_in[13];
    const float* push_W      = (const float*)d_in[14];
    const float* push_b      = (const float*)d_in[15];
    const float* pushn_W     = (const float*)d_in[16];
    const float* pushn_b     = (const float*)d_in[17];
    const float* inc_W       = (const float*)d_in[18];
    const float* inc_b       = (const float*)d_in[19];

    float* out = (float*)d_out;

    int work_blocks = (NE + 256 * EPT - 1) / (256 * EPT);   // 489
    prep_tables_kernel<<<work_blocks + NTBLK, 256>>>(
        node_states, edge_states, scalars, combine_W, combine_b,
        node_emb, edge_emb, keep_W, keep_b, push_W, push_b,
        pushn_W, pushn_b, inc_W, inc_b, train_step);
    pass1_kernel<<<work_blocks, 256>>>(edge_index, brev, scalars, batch_sc, out);
    pass2_kernel<<<(NN / 4 + 255) / 256, 256>>>(scalars, batch_sc, out,
                                                out_size > NE ? 1 : 0);
}

// round 11
// speedup vs baseline: 1.0629x; 1.0629x over previous
#include <cuda_runtime.h>
#include <stdint.h>

#define NN 100000
#define NE 1000000
#define HDIM 128
#define NHEADS 4
#define NTBLK 32      // table-builder blocks prefixed onto prep grid
#define EPT 4         // edges per thread (prep + pass1)

// ---------------- device scratch ----------------
__device__ float2        g_acc2[NN];        // per-dst {A,B}: acc = A - scalars[d]*B
__device__ double        g_loss;
__device__ int2          g_nrec[NN];        // {float_as_int(scalars[i]), node_code}
__device__ unsigned char g_ecodes[NE];
__device__ float         g_T[NHEADS][32];   // raw head dots: [h][0..15]=TE, [h][16..31]=TN
__device__ float4        g_P4[256];         // {p_inc, p_keep, p2+p3, p3} per (ce<<4)|cn
__device__ unsigned      g_cnt1 = 0;        // table completion counter
__device__ unsigned      g_done = 0;        // pass2 completion counter

__device__ __forceinline__ void red_add_f2(float2* addr, float a, float b) {
    asm volatile("red.global.add.v2.f32 [%0], {%1, %2};"
                 :: "l"(addr), "f"(a), "f"(b) : "memory");
}

// ---------------- kernel A: tables (blocks 0..31, shared-staged) + prep (rest) ----------------
__global__ void __launch_bounds__(256) prep_tables_kernel(
        const int*   __restrict__ node_states,
        const int*   __restrict__ edge_states,
        const float* __restrict__ scalars,
        const float* __restrict__ combine_W,   // (256,128)
        const float* __restrict__ combine_b,   // (128,)
        const float* __restrict__ node_emb,    // (16,128)
        const float* __restrict__ edge_emb,    // (16,128)
        const float* __restrict__ keep_W,  const float* __restrict__ keep_b,
        const float* __restrict__ push_W,  const float* __restrict__ push_b,
        const float* __restrict__ pushn_W, const float* __restrict__ pushn_b,
        const float* __restrict__ inc_W,   const float* __restrict__ inc_b,
        const int*   __restrict__ training_step) {
    int tid = threadIdx.x;
    int blk = blockIdx.x;

    if (blk >= NTBLK) {
        // ---------------- prep: EPT edges + EPT nodes per thread, coalesced strides ----------------
        int base = (blk - NTBLK) * 256 * EPT + tid;   // lane-coalesced, stride 256
        int4 es[EPT];
        #pragma unroll
        for (int k = 0; k < EPT; k++) {
            int e = base + k * 256;
            if (e < NE) es[k] = reinterpret_cast<const int4*>(edge_states)[e];  // plain load: L2-persistent
        }
        #pragma unroll
        for (int k = 0; k < EPT; k++) {
            int e = base + k * 256;
            if (e < NE)
                g_ecodes[e] = (unsigned char)(es[k].x + 2 * es[k].y + 4 * es[k].z + 8 * es[k].w);
        }
        #pragma unroll
        for (int k = 0; k < EPT; k++) {
            int i = base + k * 256;
            if (i < NN) {
                int4 s = reinterpret_cast<const int4*>(node_states)[i];
                g_nrec[i] = make_int2(__float_as_int(scalars[i]),
                                      s.x + 2 * s.y + 4 * s.z + 8 * s.w);
                g_acc2[i] = make_float2(0.f, 0.f);
            }
        }
        if (base == 0) g_loss = 0.0;
        return;
    }

    // ---------------- table block b: M[b][:] = emb_row_b @ W_half, then 4 head dots ----------------
    __shared__ float sW[32 * HDIM];      // 16KB staging (4 stages of 32 rows)
    __shared__ float sEmb[HDIM];
    __shared__ float sD[NHEADS][HDIM];   // per-head direction vectors
    __shared__ float sPart[256];
    __shared__ float sRed[NHEADS][4];    // per-warp partials for head dots
    __shared__ int   sh_last;

    int b = blk, k = b & 15;
    int base = (b < 16) ? 0 : HDIM;
    const float* embrow = ((b < 16) ? edge_emb : node_emb) + k * HDIM;

    if (tid < HDIM) sEmb[tid] = embrow[tid];
    {   // load 4 head direction vectors (512 elems, 2 per thread)
        const float* Wh[NHEADS] = {inc_W, keep_W, push_W, pushn_W};
        #pragma unroll
        for (int t = tid; t < NHEADS * HDIM; t += 256) {
            int h = t >> 7, i = t & 127;
            sD[h][i] = Wh[h][2 * i] - Wh[h][2 * i + 1];
        }
    }
    __syncthreads();

    int j = tid & 127, half = tid >> 7;
    float acc = 0.f;
    #pragma unroll
    for (int stage = 0; stage < 4; stage++) {
        // cooperative coalesced load of 32 rows (16KB) via float4: 4 per thread
        const float4* Wv = reinterpret_cast<const float4*>(combine_W + (base + stage * 32) * HDIM);
        float4* sWv = reinterpret_cast<float4*>(sW);
        #pragma unroll
        for (int t = 0; t < 4; t++)
            sWv[t * 256 + tid] = Wv[t * 256 + tid];
        __syncthreads();
        // thread (j,half) accumulates its 16 i-terms of this stage
        const float* eb = sEmb + stage * 32 + half * 16;
        const float* ws = sW + (half * 16) * HDIM + j;
        #pragma unroll
        for (int i = 0; i < 16; i++)
            acc = fmaf(eb[i], ws[i * HDIM], acc);
        __syncthreads();
    }
    sPart[tid] = acc;
    __syncthreads();

    if (tid < 128) {
        float m = sPart[tid] + sPart[tid + 128];
        float v0 = m * sD[0][tid], v1 = m * sD[1][tid];
        float v2 = m * sD[2][tid], v3 = m * sD[3][tid];
        #pragma unroll
        for (int o = 16; o > 0; o >>= 1) {
            v0 += __shfl_down_sync(0xFFFFFFFFu, v0, o);
            v1 += __shfl_down_sync(0xFFFFFFFFu, v1, o);
            v2 += __shfl_down_sync(0xFFFFFFFFu, v2, o);
            v3 += __shfl_down_sync(0xFFFFFFFFu, v3, o);
        }
        int w = tid >> 5;
        if ((tid & 31) == 0) {
            sRed[0][w] = v0; sRed[1][w] = v1; sRed[2][w] = v2; sRed[3][w] = v3;
        }
    }
    __syncthreads();
    if (tid < NHEADS)
        g_T[tid][b] = sRed[tid][0] + sRed[tid][1] + sRed[tid][2] + sRed[tid][3];

    __threadfence();
    __syncthreads();
    if (tid == 0) sh_last = (atomicAdd(&g_cnt1, 1u) == NTBLK - 1u);
    __syncthreads();
    if (!sh_last) return;

    // -------- finisher: constants + bake g_P4 --------
    __shared__ float sC[NHEADS];
    __shared__ float sT[NHEADS][32];
    const float* bh[NHEADS] = {inc_b, keep_b, push_b, pushn_b};
    if (tid < 128) {
        int h = tid >> 5, l = tid & 31;
        float c = combine_b[l] * sD[h][l]
                + combine_b[l + 32] * sD[h][l + 32]
                + combine_b[l + 64] * sD[h][l + 64]
                + combine_b[l + 96] * sD[h][l + 96];
        #pragma unroll
        for (int o = 16; o > 0; o >>= 1) c += __shfl_down_sync(0xFFFFFFFFu, c, o);
        if (l == 0) sC[h] = c + bh[h][0] - bh[h][1];
    }
    if (tid < NHEADS * 32) sT[tid >> 5][tid & 31] = g_T[tid >> 5][tid & 31];
    __syncthreads();

    int step = training_step[0];
    float tau = (step == -1) ? 0.1f
              : (1.0f + (0.1f - 1.0f) * fminf((float)step / 10000.0f, 1.0f));
    float invtau = 1.0f / tau;

    {
        int ce = tid >> 4, cn = tid & 15;
        float p[NHEADS];
        #pragma unroll
        for (int h = 0; h < NHEADS; h++) {
            float logit = (sT[h][ce] + sT[h][16 + cn] + sC[h]) * invtau;
            p[h] = 1.0f / (1.0f + __expf(-logit));
        }
        g_P4[tid] = make_float4(p[0], p[1], p[2] + p[3], p[3]);
    }
    if (tid == 0) g_cnt1 = 0;   // reset for next graph replay
}

// ---------------- kernel B: main edge pass, EPT edges/thread ----------------
__global__ void __launch_bounds__(256) pass1_kernel(const int* __restrict__ edge_index,
                                                    const int* __restrict__ brev,
                                                    const float* __restrict__ scalars,
                                                    const float* __restrict__ target,
                                                    float* __restrict__ out) {
    __shared__ float4 sP4[256];
    __shared__ float warp_sums[8];
    int tid = threadIdx.x;
    sP4[tid] = g_P4[tid];
    __syncthreads();

    int base = blockIdx.x * 256 * EPT + tid;
    float sq = 0.0f;

    int  rev[EPT], src[EPT], dst[EPT];
    float s[EPT];
    bool  v[EPT];
    #pragma unroll
    for (int k = 0; k < EPT; k++) {
        int e = base + k * 256;
        v[k] = (e < NE);
        if (v[k]) {
            rev[k] = brev[e];
            s[k] = scalars[e];
            if (e < NN) { src[k] = e; dst[k] = e; }
            else { src[k] = edge_index[e]; dst[k] = edge_index[NE + e]; }
        }
    }
    unsigned ce[EPT];
    #pragma unroll
    for (int k = 0; k < EPT; k++) if (v[k]) ce[k] = g_ecodes[rev[k]];
    int2 nr[EPT];
    #pragma unroll
    for (int k = 0; k < EPT; k++) if (v[k]) nr[k] = g_nrec[src[k]];

    #pragma unroll
    for (int k = 0; k < EPT; k++) {
        if (!v[k]) continue;
        int e = base + k * 256;
        float ssrc = __int_as_float(nr[k].x);
        float4 p = sP4[(ce[k] << 4) | (unsigned)nr[k].y];
        red_add_f2(&g_acc2[dst[k]], fmaf(p.z, s[k], p.w * ssrc), p.z);
        float ns = fmaf(s[k], p.y, p.x);
        out[e] = ns;
        if (e >= NN) { float d = target[e] - ns; sq = fmaf(d, d, sq); }
    }

    #pragma unroll
    for (int o = 16; o > 0; o >>= 1) sq += __shfl_down_sync(0xFFFFFFFFu, sq, o);
    int lane = tid & 31, wid = tid >> 5;
    if (lane == 0) warp_sums[wid] = sq;
    __syncthreads();
    if (wid == 0) {
        float vv = (lane < 8) ? warp_sums[lane] : 0.0f;
        #pragma unroll
        for (int o = 4; o > 0; o >>= 1) vv += __shfl_down_sync(0xFFFFFFFFu, vv, o);
        if (lane == 0 && vv != 0.0f) atomicAdd(&g_loss, (double)vv);
    }
}

// ---------------- kernel C: finalize first N + loss (4 elems/thread) ----------------
__global__ void __launch_bounds__(256) pass2_kernel(const float* __restrict__ scalars,
                                                    const float* __restrict__ target,
                                                    float* __restrict__ out,
                                                    int write_loss) {
    __shared__ float warp_sums[8];
    __shared__ int sh_last;
    int tid = threadIdx.x;
    int q = (blockIdx.x * blockDim.x + tid) * 4;

    float sq = 0.0f;
    if (q < NN) {                                  // NN % 4 == 0
        int p = q >> 1;
        float4 a01 = reinterpret_cast<const float4*>(g_acc2)[p];
        float4 a23 = reinterpret_cast<const float4*>(g_acc2)[p + 1];
        float4 o  = *reinterpret_cast<const float4*>(out + q);
        float4 sc = *reinterpret_cast<const float4*>(scalars + q);
        float4 tg = *reinterpret_cast<const float4*>(target + q);
        float ns0 = o.x + fmaf(-sc.x, a01.y, a01.x);
        float ns1 = o.y + fmaf(-sc.y, a01.w, a01.z);
        float ns2 = o.z + fmaf(-sc.z, a23.y, a23.x);
        float ns3 = o.w + fmaf(-sc.w, a23.w, a23.z);
        *reinterpret_cast<float4*>(out + q) = make_float4(ns0, ns1, ns2, ns3);
        float d0 = tg.x - ns0, d1 = tg.y - ns1, d2 = tg.z - ns2, d3 = tg.w - ns3;
        sq = fmaf(d0, d0, fmaf(d1, d1, fmaf(d2, d2, d3 * d3)));
    }

    #pragma unroll
    for (int o = 16; o > 0; o >>= 1) sq += __shfl_down_sync(0xFFFFFFFFu, sq, o);
    int lane = tid & 31, wid = tid >> 5;
    if (lane == 0) warp_sums[wid] = sq;
    __syncthreads();
    if (wid == 0) {
        float v = (lane < 8) ? warp_sums[lane] : 0.0f;
        #pragma unroll
        for (int o = 4; o > 0; o >>= 1) v += __shfl_down_sync(0xFFFFFFFFu, v, o);
        if (lane == 0) atomicAdd(&g_loss, (double)v);
    }

    if (tid == 0) {
        __threadfence();
        sh_last = (atomicAdd(&g_done, 1u) == gridDim.x - 1);
    }
    __syncthreads();
    if (sh_last && tid == 0) {
        if (write_loss) out[NE] = (float)(g_loss / (double)NE);
        g_done = 0;
    }
}

// ---------------- launcher ----------------
extern "C" void kernel_launch(void* const* d_in, const int* in_sizes, int n_in,
                              void* d_out, int out_size) {
    const int*   node_states = (const int*)  d_in[0];
    const int*   edge_states = (const int*)  d_in[1];
    const float* scalars     = (const float*)d_in[2];
    const int*   edge_index  = (const int*)  d_in[3];
    const int*   brev        = (const int*)  d_in[4];
    const float* batch_sc    = (const float*)d_in[5];
    const int*   train_step  = (const int*)  d_in[7];
    const float* node_emb    = (const float*)d_in[8];
    const float* edge_emb    = (const float*)d_in[9];
    const float* combine_W   = (const float*)d_in[10];
    const float* combine_b   = (const float*)d_in[11];
    const float* keep_W      = (const float*)d_in[12];
    const float* keep_b      = (const float*)d_in[13];
    const float* push_W      = (const float*)d_in[14];
    const float* push_b      = (const float*)d_in[15];
    const float* pushn_W     = (const float*)d_in[16];
    const float* pushn_b     = (const float*)d_in[17];
    const float* inc_W       = (const float*)d_in[18];
    const float* inc_b       = (const float*)d_in[19];

    float* out = (float*)d_out;

    int work_blocks = (NE + 256 * EPT - 1) / (256 * EPT);   // 977
    prep_tables_kernel<<<work_blocks + NTBLK, 256>>>(
        node_states, edge_states, scalars, combine_W, combine_b,
        node_emb, edge_emb, keep_W, keep_b, push_W, push_b,
        pushn_W, pushn_b, inc_W, inc_b, train_step);
    pass1_kernel<<<work_blocks, 256>>>(edge_index, brev, scalars, batch_sc, out);
    pass2_kernel<<<(NN / 4 + 255) / 256, 256>>>(scalars, batch_sc, out,
                                                out_size > NE ? 1 : 0);
}

// round 12
// speedup vs baseline: 1.1501x; 1.0820x over previous
#include <cuda_runtime.h>
#include <stdint.h>

#define NN 100000
#define NE 1000000
#define HDIM 128
#define NHEADS 4
#define NTBLK 32                  // table-builder blocks
#define NODEBLK 391               // node-prep blocks (391*256 >= NN)
#define EPT 4                     // edges per thread
#define EDGEBLK ((NE + 256*EPT - 1) / (256*EPT))   // 977

// ---------------- device scratch ----------------
__device__ float2        g_acc2[NN];        // per-dst {A,B}: acc = A - scalars[d]*B
__device__ double        g_loss;
__device__ int2          g_nrec[NN];        // {float_as_int(scalars[i]), node_code}
__device__ unsigned char g_ecodes[NE];
__device__ float         g_T[NHEADS][32];   // raw head dots
__device__ float4        g_P4[256];         // {p_inc, p_keep, p2+p3, p3} per (ce<<4)|cn
__device__ unsigned      g_cnt1 = 0;
__device__ unsigned      g_done = 0;

__device__ __forceinline__ void red_add_f2(float2* addr, float a, float b) {
    asm volatile("red.global.add.v2.f32 [%0], {%1, %2};"
                 :: "l"(addr), "f"(a), "f"(b) : "memory");
}
__device__ __forceinline__ void gdc_launch_dependents() {
    asm volatile("griddepcontrol.launch_dependents;");
}
__device__ __forceinline__ void gdc_wait() {
    asm volatile("griddepcontrol.wait;" ::: "memory");
}
// 16B load with 256B L2 prefetch-width hint (request-rate limited streams)
__device__ __forceinline__ int4 ldg_256B(const int4* p) {
    int4 r;
    asm volatile("ld.global.L2::256B.v4.u32 {%0,%1,%2,%3}, [%4];"
                 : "=r"(r.x), "=r"(r.y), "=r"(r.z), "=r"(r.w) : "l"(p));
    return r;
}

// ---------------- kernel A: tables + node prep + edge-code stream ----------------
__global__ void __launch_bounds__(256) prep_tables_kernel(
        const int*   __restrict__ node_states,
        const int*   __restrict__ edge_states,
        const float* __restrict__ scalars,
        const float* __restrict__ combine_W,   // (256,128)
        const float* __restrict__ combine_b,   // (128,)
        const float* __restrict__ node_emb,    // (16,128)
        const float* __restrict__ edge_emb,    // (16,128)
        const float* __restrict__ keep_W,  const float* __restrict__ keep_b,
        const float* __restrict__ push_W,  const float* __restrict__ push_b,
        const float* __restrict__ pushn_W, const float* __restrict__ pushn_b,
        const float* __restrict__ inc_W,   const float* __restrict__ inc_b,
        const int*   __restrict__ training_step) {
    int tid = threadIdx.x;
    int blk = blockIdx.x;

    if (blk >= NTBLK + NODEBLK) {
        // ---------------- edge-code stream: EPT edges per thread ----------------
        int base = (blk - NTBLK - NODEBLK) * 256 * EPT + tid;
        int4 es[EPT];
        #pragma unroll
        for (int k = 0; k < EPT; k++) {
            int e = base + k * 256;
            if (e < NE) es[k] = ldg_256B(reinterpret_cast<const int4*>(edge_states) + e);
        }
        #pragma unroll
        for (int k = 0; k < EPT; k++) {
            int e = base + k * 256;
            if (e < NE)
                g_ecodes[e] = (unsigned char)(es[k].x + 2 * es[k].y + 4 * es[k].z + 8 * es[k].w);
        }
        gdc_launch_dependents();
        return;
    }
    if (blk >= NTBLK) {
        // ---------------- node prep ----------------
        int i = (blk - NTBLK) * 256 + tid;
        if (i < NN) {
            int4 s = ldg_256B(reinterpret_cast<const int4*>(node_states) + i);
            g_nrec[i] = make_int2(__float_as_int(scalars[i]),
                                  s.x + 2 * s.y + 4 * s.z + 8 * s.w);
            g_acc2[i] = make_float2(0.f, 0.f);
        }
        if (i == 0) g_loss = 0.0;
        gdc_launch_dependents();
        return;
    }

    // ---------------- table block b (shared-staged GEMV) ----------------
    __shared__ float sW[32 * HDIM];      // 16KB staging (4 stages of 32 rows)
    __shared__ float sEmb[HDIM];
    __shared__ float sD[NHEADS][HDIM];
    __shared__ float sPart[256];
    __shared__ float sRed[NHEADS][4];
    __shared__ int   sh_last;

    int b = blk, k = b & 15;
    int base = (b < 16) ? 0 : HDIM;
    const float* embrow = ((b < 16) ? edge_emb : node_emb) + k * HDIM;

    if (tid < HDIM) sEmb[tid] = embrow[tid];
    {
        const float* Wh[NHEADS] = {inc_W, keep_W, push_W, pushn_W};
        #pragma unroll
        for (int t = tid; t < NHEADS * HDIM; t += 256) {
            int h = t >> 7, i = t & 127;
            sD[h][i] = Wh[h][2 * i] - Wh[h][2 * i + 1];
        }
    }
    __syncthreads();

    int j = tid & 127, half = tid >> 7;
    float acc = 0.f;
    #pragma unroll
    for (int stage = 0; stage < 4; stage++) {
        const float4* Wv = reinterpret_cast<const float4*>(combine_W + (base + stage * 32) * HDIM);
        float4* sWv = reinterpret_cast<float4*>(sW);
        #pragma unroll
        for (int t = 0; t < 4; t++)
            sWv[t * 256 + tid] = Wv[t * 256 + tid];
        __syncthreads();
        const float* eb = sEmb + stage * 32 + half * 16;
        const float* ws = sW + (half * 16) * HDIM + j;
        #pragma unroll
        for (int i = 0; i < 16; i++)
            acc = fmaf(eb[i], ws[i * HDIM], acc);
        __syncthreads();
    }
    sPart[tid] = acc;
    __syncthreads();

    if (tid < 128) {
        float m = sPart[tid] + sPart[tid + 128];
        float v0 = m * sD[0][tid], v1 = m * sD[1][tid];
        float v2 = m * sD[2][tid], v3 = m * sD[3][tid];
        #pragma unroll
        for (int o = 16; o > 0; o >>= 1) {
            v0 += __shfl_down_sync(0xFFFFFFFFu, v0, o);
            v1 += __shfl_down_sync(0xFFFFFFFFu, v1, o);
            v2 += __shfl_down_sync(0xFFFFFFFFu, v2, o);
            v3 += __shfl_down_sync(0xFFFFFFFFu, v3, o);
        }
        int w = tid >> 5;
        if ((tid & 31) == 0) {
            sRed[0][w] = v0; sRed[1][w] = v1; sRed[2][w] = v2; sRed[3][w] = v3;
        }
    }
    __syncthreads();
    if (tid < NHEADS)
        g_T[tid][b] = sRed[tid][0] + sRed[tid][1] + sRed[tid][2] + sRed[tid][3];

    __threadfence();
    __syncthreads();
    if (tid == 0) sh_last = (atomicAdd(&g_cnt1, 1u) == NTBLK - 1u);
    __syncthreads();
    if (!sh_last) { gdc_launch_dependents(); return; }

    // -------- finisher: constants + bake g_P4 --------
    __shared__ float sC[NHEADS];
    __shared__ float sT[NHEADS][32];
    const float* bh[NHEADS] = {inc_b, keep_b, push_b, pushn_b};
    if (tid < 128) {
        int h = tid >> 5, l = tid & 31;
        float c = combine_b[l] * sD[h][l]
                + combine_b[l + 32] * sD[h][l + 32]
                + combine_b[l + 64] * sD[h][l + 64]
                + combine_b[l + 96] * sD[h][l + 96];
        #pragma unroll
        for (int o = 16; o > 0; o >>= 1) c += __shfl_down_sync(0xFFFFFFFFu, c, o);
        if (l == 0) sC[h] = c + bh[h][0] - bh[h][1];
    }
    if (tid < NHEADS * 32) sT[tid >> 5][tid & 31] = g_T[tid >> 5][tid & 31];
    __syncthreads();

    int step = training_step[0];
    float tau = (step == -1) ? 0.1f
              : (1.0f + (0.1f - 1.0f) * fminf((float)step / 10000.0f, 1.0f));
    float invtau = 1.0f / tau;

    {
        int ce = tid >> 4, cn = tid & 15;
        float p[NHEADS];
        #pragma unroll
        for (int h = 0; h < NHEADS; h++) {
            float logit = (sT[h][ce] + sT[h][16 + cn] + sC[h]) * invtau;
            p[h] = 1.0f / (1.0f + __expf(-logit));
        }
        g_P4[tid] = make_float4(p[0], p[1], p[2] + p[3], p[3]);
    }
    if (tid == 0) g_cnt1 = 0;   // reset for next graph replay
    gdc_launch_dependents();
}

// ---------------- kernel B: main edge pass (PDL: independent prefix, then wait) ----------------
__global__ void __launch_bounds__(256) pass1_kernel(const int* __restrict__ edge_index,
                                                    const int* __restrict__ brev,
                                                    const float* __restrict__ scalars,
                                                    const float* __restrict__ target,
                                                    float* __restrict__ out) {
    __shared__ float4 sP4[256];
    __shared__ float warp_sums[8];
    int tid = threadIdx.x;

    int base = blockIdx.x * 256 * EPT + tid;
    float sq = 0.0f;

    // ---- independent prefix: pure-input coalesced loads (overlap with prep) ----
    int  rev[EPT], src[EPT], dst[EPT];
    float s[EPT];
    bool  v[EPT];
    #pragma unroll
    for (int k = 0; k < EPT; k++) {
        int e = base + k * 256;
        v[k] = (e < NE);
        if (v[k]) {
            rev[k] = brev[e];
            s[k] = scalars[e];
            if (e < NN) { src[k] = e; dst[k] = e; }
            else { src[k] = edge_index[e]; dst[k] = edge_index[NE + e]; }
        }
    }

    // ---- wait for prep completion, then dependent work ----
    gdc_wait();
    sP4[tid] = g_P4[tid];
    __syncthreads();

    unsigned ce[EPT];
    #pragma unroll
    for (int k = 0; k < EPT; k++) if (v[k]) ce[k] = g_ecodes[rev[k]];
    int2 nr[EPT];
    #pragma unroll
    for (int k = 0; k < EPT; k++) if (v[k]) nr[k] = g_nrec[src[k]];

    #pragma unroll
    for (int k = 0; k < EPT; k++) {
        if (!v[k]) continue;
        int e = base + k * 256;
        float ssrc = __int_as_float(nr[k].x);
        float4 p = sP4[(ce[k] << 4) | (unsigned)nr[k].y];
        red_add_f2(&g_acc2[dst[k]], fmaf(p.z, s[k], p.w * ssrc), p.z);
        float ns = fmaf(s[k], p.y, p.x);
        out[e] = ns;
        if (e >= NN) { float d = target[e] - ns; sq = fmaf(d, d, sq); }
    }
    gdc_launch_dependents();

    #pragma unroll
    for (int o = 16; o > 0; o >>= 1) sq += __shfl_down_sync(0xFFFFFFFFu, sq, o);
    int lane = tid & 31, wid = tid >> 5;
    if (lane == 0) warp_sums[wid] = sq;
    __syncthreads();
    if (wid == 0) {
        float vv = (lane < 8) ? warp_sums[lane] : 0.0f;
        #pragma unroll
        for (int o = 4; o > 0; o >>= 1) vv += __shfl_down_sync(0xFFFFFFFFu, vv, o);
        if (lane == 0 && vv != 0.0f) atomicAdd(&g_loss, (double)vv);
    }
}

// ---------------- kernel C: finalize first N + loss (PDL prefix) ----------------
__global__ void __launch_bounds__(256) pass2_kernel(const float* __restrict__ scalars,
                                                    const float* __restrict__ target,
                                                    float* __restrict__ out,
                                                    int write_loss) {
    __shared__ float warp_sums[8];
    __shared__ int sh_last;
    int tid = threadIdx.x;
    int q = (blockIdx.x * blockDim.x + tid) * 4;

    // independent prefix (inputs only)
    float4 sc = make_float4(0.f, 0.f, 0.f, 0.f), tg = sc;
    if (q < NN) {
        sc = *reinterpret_cast<const float4*>(scalars + q);
        tg = *reinterpret_cast<const float4*>(target + q);
    }

    gdc_wait();

    float sq = 0.0f;
    if (q < NN) {                                  // NN % 4 == 0
        int p = q >> 1;
        float4 a01 = reinterpret_cast<const float4*>(g_acc2)[p];
        float4 a23 = reinterpret_cast<const float4*>(g_acc2)[p + 1];
        float4 o  = *reinterpret_cast<const float4*>(out + q);
        float ns0 = o.x + fmaf(-sc.x, a01.y, a01.x);
        float ns1 = o.y + fmaf(-sc.y, a01.w, a01.z);
        float ns2 = o.z + fmaf(-sc.z, a23.y, a23.x);
        float ns3 = o.w + fmaf(-sc.w, a23.w, a23.z);
        *reinterpret_cast<float4*>(out + q) = make_float4(ns0, ns1, ns2, ns3);
        float d0 = tg.x - ns0, d1 = tg.y - ns1, d2 = tg.z - ns2, d3 = tg.w - ns3;
        sq = fmaf(d0, d0, fmaf(d1, d1, fmaf(d2, d2, d3 * d3)));
    }

    #pragma unroll
    for (int o = 16; o > 0; o >>= 1) sq += __shfl_down_sync(0xFFFFFFFFu, sq, o);
    int lane = tid & 31, wid = tid >> 5;
    if (lane == 0) warp_sums[wid] = sq;
    __syncthreads();
    if (wid == 0) {
        float v = (lane < 8) ? warp_sums[lane] : 0.0f;
        #pragma unroll
        for (int o = 4; o > 0; o >>= 1) v += __shfl_down_sync(0xFFFFFFFFu, v, o);
        if (lane == 0) atomicAdd(&g_loss, (double)v);
    }

    if (tid == 0) {
        __threadfence();
        sh_last = (atomicAdd(&g_done, 1u) == gridDim.x - 1);
    }
    __syncthreads();
    if (sh_last && tid == 0) {
        if (write_loss) out[NE] = (float)(g_loss / (double)NE);
        g_done = 0;
    }
}

// ---------------- launcher ----------------
extern "C" void kernel_launch(void* const* d_in, const int* in_sizes, int n_in,
                              void* d_out, int out_size) {
    const int*   node_states = (const int*)  d_in[0];
    const int*   edge_states = (const int*)  d_in[1];
    const float* scalars     = (const float*)d_in[2];
    const int*   edge_index  = (const int*)  d_in[3];
    const int*   brev        = (const int*)  d_in[4];
    const float* batch_sc    = (const float*)d_in[5];
    const int*   train_step  = (const int*)  d_in[7];
    const float* node_emb    = (const float*)d_in[8];
    const float* edge_emb    = (const float*)d_in[9];
    const float* combine_W   = (const float*)d_in[10];
    const float* combine_b   = (const float*)d_in[11];
    const float* keep_W      = (const float*)d_in[12];
    const float* keep_b      = (const float*)d_in[13];
    const float* push_W      = (const float*)d_in[14];
    const float* push_b      = (const float*)d_in[15];
    const float* pushn_W     = (const float*)d_in[16];
    const float* pushn_b     = (const float*)d_in[17];
    const float* inc_W       = (const float*)d_in[18];
    const float* inc_b       = (const float*)d_in[19];

    float* out = (float*)d_out;

    prep_tables_kernel<<<NTBLK + NODEBLK + EDGEBLK, 256>>>(
        node_states, edge_states, scalars, combine_W, combine_b,
        node_emb, edge_emb, keep_W, keep_b, push_W, push_b,
        pushn_W, pushn_b, inc_W, inc_b, train_step);

    cudaLaunchAttribute pdl[1];
    pdl[0].id = cudaLaunchAttributeProgrammaticStreamSerialization;
    pdl[0].val.programmaticStreamSerializationAllowed = 1;

    {
        cudaLaunchConfig_t cfg = {};
        cfg.gridDim = dim3(EDGEBLK, 1, 1);
        cfg.blockDim = dim3(256, 1, 1);
        cfg.attrs = pdl;
        cfg.numAttrs = 1;
        cudaLaunchKernelEx(&cfg, pass1_kernel, edge_index, brev, scalars, batch_sc, out);
    }
    {
        cudaLaunchConfig_t cfg = {};
        cfg.gridDim = dim3((NN / 4 + 255) / 256, 1, 1);
        cfg.blockDim = dim3(256, 1, 1);
        cfg.attrs = pdl;
        cfg.numAttrs = 1;
        int wl = out_size > NE ? 1 : 0;
        cudaLaunchKernelEx(&cfg, pass2_kernel, scalars, batch_sc, out, wl);
    }
}